// round 16
// baseline (speedup 1.0000x reference)
#include <cuda_runtime.h>
#include <cstdint>

// ---------------------------------------------------------------------------
// APPNP. GEMM1: tf32 mma.sync, CTA 128x128, 2-stage cp.async, B pre-rounded
// (RNA) in g_w1r. Propagation in degree-sorted RENUMBERED space: h0/norms/CSR
// permuted once; agg contiguous + divergence-free; scatter only on final write.
// ---------------------------------------------------------------------------

#define N_NODES 100000
#define E_EDGES 1600000
#define OUT_DIM 48
#define HID_DIM 256
#define IN_DIM  512
#define NBINS   1024

// Scratch (device globals — allocation APIs are forbidden)
__device__ __align__(16) float g_hidden[(size_t)N_NODES * HID_DIM];
__device__ __align__(16) float g_w1r[(size_t)IN_DIM * HID_DIM];   // RNA-rounded W1
__device__ __align__(16) float g_h0[(size_t)N_NODES * OUT_DIM];   // old space
__device__ __align__(16) float g_h0s[(size_t)N_NODES * OUT_DIM];  // sorted space
__device__ __align__(16) float g_hsA[(size_t)N_NODES * OUT_DIM];
__device__ __align__(16) float g_hsB[(size_t)N_NODES * OUT_DIM];
__device__ int   g_ideg_out[N_NODES];
__device__ int   g_ideg_in[N_NODES];
__device__ int   g_ideg_s[N_NODES];      // sorted-space in-degree
__device__ float g_nin_s[N_NODES];       // sorted-space norm_in
__device__ float g_nout_s[N_NODES];      // sorted-space norm_out
__device__ int   g_off[N_NODES + 1];     // sorted-space CSR offsets
__device__ int   g_cursor[N_NODES];
__device__ int   g_blocksums[512];
__device__ int   g_csr_src[E_EDGES];     // sorted-space src ids
__device__ int   g_hist[NBINS];
__device__ int   g_hist_cur[NBINS];
__device__ int   g_perm[N_NODES];        // perm[new] = old
__device__ int   g_inv[N_NODES];         // inv[old] = new

// ---------------------------------------------------------------------------
// Degrees
// ---------------------------------------------------------------------------
__global__ void zero_deg_kernel(int n) {
    int i = blockIdx.x * blockDim.x + threadIdx.x;
    if (i < n) { g_ideg_out[i] = 0; g_ideg_in[i] = 0; }
    if (i < NBINS) g_hist[i] = 0;
}
__global__ void deg_kernel(const int* __restrict__ src, const int* __restrict__ dst, int e) {
    int i = blockIdx.x * blockDim.x + threadIdx.x;
    if (i < e) {
        atomicAdd(&g_ideg_out[src[i]], 1);
        atomicAdd(&g_ideg_in[dst[i]], 1);
    }
}

// ---------------------------------------------------------------------------
// Degree-sorted permutation (counting sort by in-degree) + inverse
// ---------------------------------------------------------------------------
__global__ void hist_kernel(int n) {
    int i = blockIdx.x * blockDim.x + threadIdx.x;
    if (i < n) atomicAdd(&g_hist[min(g_ideg_in[i], NBINS - 1)], 1);
}
__global__ void hist_scan_kernel() {
    __shared__ int sh[NBINS];
    int t = threadIdx.x;
    sh[t] = g_hist[t];
    __syncthreads();
#pragma unroll
    for (int d = 1; d < NBINS; d <<= 1) {
        int x = (t >= d) ? sh[t - d] : 0;
        __syncthreads();
        sh[t] += x;
        __syncthreads();
    }
    g_hist_cur[t] = (t > 0) ? sh[t - 1] : 0;
}
__global__ void perm_kernel(int n) {
    int i = blockIdx.x * blockDim.x + threadIdx.x;
    if (i < n) {
        int b = min(g_ideg_in[i], NBINS - 1);
        int p = atomicAdd(&g_hist_cur[b], 1);
        g_perm[p] = i;
    }
}
__global__ void inv_kernel(int n) {
    int i = blockIdx.x * blockDim.x + threadIdx.x;
    if (i < n) g_inv[g_perm[i]] = i;
}
__global__ void sdeg_kernel(int n) {
    int i = blockIdx.x * blockDim.x + threadIdx.x;
    if (i < n) {
        int old = g_perm[i];
        int di = g_ideg_in[old];
        g_ideg_s[i] = di;
        g_nin_s[i]  = rsqrtf((float)max(di, 1));
        g_nout_s[i] = rsqrtf((float)max(g_ideg_out[old], 1));
    }
}

// ---------------------------------------------------------------------------
// Prefix sum over g_ideg_s -> g_off (sorted space)
// ---------------------------------------------------------------------------
__global__ void scanA_kernel(int n) {
    __shared__ int sh[256];
    int i = blockIdx.x * 256 + threadIdx.x;
    sh[threadIdx.x] = (i < n) ? g_ideg_s[i] : 0;
    __syncthreads();
#pragma unroll
    for (int d = 1; d < 256; d <<= 1) {
        int t = (threadIdx.x >= d) ? sh[threadIdx.x - d] : 0;
        __syncthreads();
        sh[threadIdx.x] += t;
        __syncthreads();
    }
    if (i < n) g_off[i + 1] = sh[threadIdx.x];
    if (threadIdx.x == 255) g_blocksums[blockIdx.x] = sh[255];
}
__global__ void scanB_kernel(int nb) {
    __shared__ int sh[512];
    int t = threadIdx.x;
    sh[t] = (t < nb) ? g_blocksums[t] : 0;
    __syncthreads();
#pragma unroll
    for (int d = 1; d < 512; d <<= 1) {
        int x = (t >= d) ? sh[t - d] : 0;
        __syncthreads();
        sh[t] += x;
        __syncthreads();
    }
    if (t < nb) g_blocksums[t] = sh[t];
}
__global__ void scanC_kernel(int n) {
    int i = blockIdx.x * 256 + threadIdx.x;
    if (i < n) {
        int add = (blockIdx.x > 0) ? g_blocksums[blockIdx.x - 1] : 0;
        g_off[i + 1] += add;
    }
    if (i == 0) g_off[0] = 0;
}
__global__ void cursor_init_kernel(int n) {
    int i = blockIdx.x * blockDim.x + threadIdx.x;
    if (i < n) g_cursor[i] = g_off[i];
}
// CSR build entirely in sorted space
__global__ void scatter_kernel(const int* __restrict__ src, const int* __restrict__ dst, int e) {
    int i = blockIdx.x * blockDim.x + threadIdx.x;
    if (i < e) {
        int p = atomicAdd(&g_cursor[g_inv[dst[i]]], 1);
        g_csr_src[p] = g_inv[src[i]];
    }
}

// ---------------------------------------------------------------------------
// tf32 helpers
// ---------------------------------------------------------------------------
__device__ __forceinline__ uint32_t rna_tf32_f(float x) {
    uint32_t u;
    asm("cvt.rna.tf32.f32 %0, %1;" : "=r"(u) : "f"(x));
    return u;
}
__device__ __forceinline__ void mma_tf32(float c[4],
                                         uint32_t a0, uint32_t a1, uint32_t a2, uint32_t a3,
                                         uint32_t b0, uint32_t b1)
{
    asm volatile(
        "mma.sync.aligned.m16n8k8.row.col.f32.tf32.tf32.f32 "
        "{%0,%1,%2,%3}, {%4,%5,%6,%7}, {%8,%9}, {%0,%1,%2,%3};"
        : "+f"(c[0]), "+f"(c[1]), "+f"(c[2]), "+f"(c[3])
        : "r"(a0), "r"(a1), "r"(a2), "r"(a3), "r"(b0), "r"(b1));
}
__device__ __forceinline__ uint32_t smem_u32(const void* p) {
    uint32_t a;
    asm("{ .reg .u64 t; cvta.to.shared.u64 t, %1; cvt.u32.u64 %0, t; }" : "=r"(a) : "l"(p));
    return a;
}
__device__ __forceinline__ void cp16(uint32_t dst, const void* src, int szbytes) {
    asm volatile("cp.async.cg.shared.global [%0], [%1], 16, %2;"
                 :: "r"(dst), "l"(src), "r"(szbytes));
}
#define CP_COMMIT() asm volatile("cp.async.commit_group;" ::: "memory")
#define CP_WAIT(n)  asm volatile("cp.async.wait_group %0;" :: "n"(n) : "memory")

// W1 pre-round (RNA): mma's RZ truncation of this is the identity
__global__ void w1_round_kernel(const float* __restrict__ W1) {
    int i = blockIdx.x * blockDim.x + threadIdx.x;
    if (i < IN_DIM * HID_DIM)
        g_w1r[i] = __uint_as_float(rna_tf32_f(W1[i]));
}

// ---------------------------------------------------------------------------
// GEMM1 (tf32 mma.sync, 2-stage cp.async, CTA 128x128 — exact R15 structure)
// ---------------------------------------------------------------------------
#define G1_AS_STRIDE 20
#define G1_BS_STRIDE 136
#define G1_NCHUNK    (IN_DIM / 16)   // 32

__global__ __launch_bounds__(256, 2) void gemm1_mma_kernel(
    const float* __restrict__ A, const float* __restrict__ bias, int M)
{
    __shared__ uint32_t As[2][128][G1_AS_STRIDE];
    __shared__ uint32_t Bs[2][16][G1_BS_STRIDE];

    const int tid  = threadIdx.x;
    const int wid  = tid >> 5;
    const int lane = tid & 31;
    const int warpM = wid & 3;
    const int warpN = wid >> 2;
    const int m0 = blockIdx.y * 128;
    const int n0 = blockIdx.x * 128;

    const int grp = lane >> 2;
    const int qid = lane & 3;

    const int a_m0 = tid >> 2;
    const int a_k0 = (tid & 3) * 4;
    const int a_m1 = (tid + 256) >> 2;
    const int a_k1 = ((tid + 256) & 3) * 4;
    const int b_kk0 = tid >> 5;
    const int b_nn0 = (tid & 31) * 4;
    const int b_kk1 = (tid + 256) >> 5;
    const int b_nn1 = ((tid + 256) & 31) * 4;

    float acc[2][8][4];
#pragma unroll
    for (int mt = 0; mt < 2; mt++)
#pragma unroll
        for (int nt = 0; nt < 8; nt++)
#pragma unroll
            for (int q = 0; q < 4; q++) acc[mt][nt][q] = 0.f;

    auto issue = [&](int kc, int b) {
        const int k0 = kc * 16;
        const uint32_t abase = smem_u32(&As[b][0][0]);
        const uint32_t bbase = smem_u32(&Bs[b][0][0]);
        int sz0 = (m0 + a_m0 < M) ? 16 : 0;
        cp16(abase + (uint32_t)(a_m0 * G1_AS_STRIDE + a_k0) * 4,
             &A[(size_t)(m0 + a_m0) * IN_DIM + k0 + a_k0], sz0);
        int sz1 = (m0 + a_m1 < M) ? 16 : 0;
        cp16(abase + (uint32_t)(a_m1 * G1_AS_STRIDE + a_k1) * 4,
             &A[(size_t)(m0 + a_m1) * IN_DIM + k0 + a_k1], sz1);
        cp16(bbase + (uint32_t)(b_kk0 * G1_BS_STRIDE + b_nn0) * 4,
             &g_w1r[(size_t)(k0 + b_kk0) * HID_DIM + n0 + b_nn0], 16);
        cp16(bbase + (uint32_t)(b_kk1 * G1_BS_STRIDE + b_nn1) * 4,
             &g_w1r[(size_t)(k0 + b_kk1) * HID_DIM + n0 + b_nn1], 16);
        CP_COMMIT();
    };

    issue(0, 0);
    issue(1, 1);

    for (int kc = 0; kc < G1_NCHUNK; kc++) {
        const int b = kc & 1;
        if (kc + 1 < G1_NCHUNK) { CP_WAIT(1); } else { CP_WAIT(0); }
        __syncthreads();

#pragma unroll
        for (int ks = 0; ks < 2; ks++) {
            const int k = ks * 8;
            uint32_t bf[8][2];
#pragma unroll
            for (int nt = 0; nt < 8; nt++) {
                int cn = warpN * 64 + nt * 8 + grp;
                bf[nt][0] = Bs[b][k + qid][cn];
                bf[nt][1] = Bs[b][k + 4 + qid][cn];
            }
#pragma unroll
            for (int mt = 0; mt < 2; mt++) {
                int rm = warpM * 32 + mt * 16 + grp;
                uint32_t a0 = As[b][rm][k + qid];
                uint32_t a1 = As[b][rm + 8][k + qid];
                uint32_t a2 = As[b][rm][k + 4 + qid];
                uint32_t a3 = As[b][rm + 8][k + 4 + qid];
#pragma unroll
                for (int nt = 0; nt < 8; nt++)
                    mma_tf32(acc[mt][nt], a0, a1, a2, a3, bf[nt][0], bf[nt][1]);
            }
        }
        __syncthreads();
        if (kc + 2 < G1_NCHUNK) issue(kc + 2, b);
    }

#pragma unroll
    for (int nt = 0; nt < 8; nt++) {
        int col = n0 + warpN * 64 + nt * 8 + 2 * qid;
        float bb0 = __ldg(&bias[col]);
        float bb1 = __ldg(&bias[col + 1]);
#pragma unroll
        for (int mt = 0; mt < 2; mt++) {
            int r0 = m0 + warpM * 32 + mt * 16 + grp;
            if (r0 < M) {
                float2 v = make_float2(fmaxf(acc[mt][nt][0] + bb0, 0.f),
                                       fmaxf(acc[mt][nt][1] + bb1, 0.f));
                *(float2*)&g_hidden[(size_t)r0 * HID_DIM + col] = v;
            }
            if (r0 + 8 < M) {
                float2 v = make_float2(fmaxf(acc[mt][nt][2] + bb0, 0.f),
                                       fmaxf(acc[mt][nt][3] + bb1, 0.f));
                *(float2*)&g_hidden[(size_t)(r0 + 8) * HID_DIM + col] = v;
            }
        }
    }
}

// ---------------------------------------------------------------------------
// GEMM2: h0 = hidden[M,256] @ W2[256,48] + b2  (SIMT, old space)
// ---------------------------------------------------------------------------
__global__ __launch_bounds__(256) void gemm2_kernel(
    const float* __restrict__ W2, const float* __restrict__ b2, int M)
{
    __shared__ float Ws[64][48];
    const int tid = threadIdx.x;
    const int row = blockIdx.x * 128 + (tid >> 1);
    const int half = tid & 1;
    const bool ok = (row < M);

    float acc[24];
#pragma unroll
    for (int j = 0; j < 24; j++) acc[j] = 0.f;

    const float4* hid4 = (const float4*)g_hidden;
    for (int kc = 0; kc < 4; kc++) {
        __syncthreads();
        for (int i = tid; i < 64 * 48; i += 256) {
            int kk = i / 48, c = i - kk * 48;
            Ws[kk][c] = W2[(kc * 64 + kk) * 48 + c];
        }
        __syncthreads();
        if (ok) {
#pragma unroll
            for (int k4 = 0; k4 < 16; k4++) {
                float4 a = hid4[(size_t)row * 64 + kc * 16 + k4];
                float av[4] = {a.x, a.y, a.z, a.w};
#pragma unroll
                for (int q = 0; q < 4; q++)
#pragma unroll
                    for (int j = 0; j < 24; j++)
                        acc[j] += av[q] * Ws[k4 * 4 + q][half * 24 + j];
            }
        }
    }
    if (ok) {
#pragma unroll
        for (int j = 0; j < 24; j++)
            g_h0[(size_t)row * 48 + half * 24 + j] = acc[j] + b2[half * 24 + j];
    }
}

// ---------------------------------------------------------------------------
// Propagation (sorted space)
// ---------------------------------------------------------------------------
__global__ void h0perm_kernel(int n4) {
    int i = blockIdx.x * blockDim.x + threadIdx.x;
    if (i >= n4) return;
    int row = i / 12, c = i - row * 12;
    int old = g_perm[row];
    ((float4*)g_h0s)[i] = ((const float4*)g_h0)[(size_t)old * 12 + c];
}
__global__ void hs0_kernel(int n4) {
    int i = blockIdx.x * blockDim.x + threadIdx.x;
    if (i >= n4) return;
    int row = i / 12;
    float no = g_nout_s[row];
    float4 v = ((const float4*)g_h0s)[i];
    ((float4*)g_hsA)[i] = make_float4(v.x * no, v.y * no, v.z * no, v.w * no);
}

__global__ __launch_bounds__(384) void agg_kernel(
    float* __restrict__ dout, int parity, int last, int n)
{
    int t = blockIdx.x * 384 + threadIdx.x;
    int g = t / 12;
    int c = t - g * 12;
    if (g >= n) return;

    const float4* hin  = (const float4*)(parity ? g_hsB : g_hsA);
    float4*       hout = (float4*)(parity ? g_hsA : g_hsB);

    int i   = g_off[g];
    int end = g_off[g + 1];
    float4 acc = make_float4(0.f, 0.f, 0.f, 0.f);

    for (; i + 3 < end; i += 4) {
        int s0 = __ldg(&g_csr_src[i]);
        int s1 = __ldg(&g_csr_src[i + 1]);
        int s2 = __ldg(&g_csr_src[i + 2]);
        int s3 = __ldg(&g_csr_src[i + 3]);
        float4 v0 = hin[(size_t)s0 * 12 + c];
        float4 v1 = hin[(size_t)s1 * 12 + c];
        float4 v2 = hin[(size_t)s2 * 12 + c];
        float4 v3 = hin[(size_t)s3 * 12 + c];
        acc.x += v0.x + v1.x + v2.x + v3.x;
        acc.y += v0.y + v1.y + v2.y + v3.y;
        acc.z += v0.z + v1.z + v2.z + v3.z;
        acc.w += v0.w + v1.w + v2.w + v3.w;
    }
    for (; i < end; i++) {
        int s = __ldg(&g_csr_src[i]);
        float4 v = hin[(size_t)s * 12 + c];
        acc.x += v.x; acc.y += v.y; acc.z += v.z; acc.w += v.w;
    }

    float ni = g_nin_s[g];
    float4 z = ((const float4*)g_h0s)[(size_t)g * 12 + c];
    float4 h = make_float4(0.9f * acc.x * ni + 0.1f * z.x,
                           0.9f * acc.y * ni + 0.1f * z.y,
                           0.9f * acc.z * ni + 0.1f * z.z,
                           0.9f * acc.w * ni + 0.1f * z.w);
    if (last) {
        int old = __ldg(&g_perm[g]);
        ((float4*)dout)[(size_t)old * 12 + c] = h;
    } else {
        float no = g_nout_s[g];
        hout[(size_t)g * 12 + c] = make_float4(h.x * no, h.y * no, h.z * no, h.w * no);
    }
}

// ---------------------------------------------------------------------------
extern "C" void kernel_launch(void* const* d_in, const int* in_sizes, int n_in,
                              void* d_out, int out_size)
{
    const float* feats = (const float*)d_in[0];
    const int*   src   = (const int*)d_in[1];
    const int*   dst   = (const int*)d_in[2];
    const float* W1    = (const float*)d_in[3];
    const float* b1    = (const float*)d_in[4];
    const float* W2    = (const float*)d_in[5];
    const float* b2    = (const float*)d_in[6];

    const int N = in_sizes[0] / IN_DIM;
    const int E = in_sizes[1];

    // degrees
    zero_deg_kernel<<<(N + 255) / 256, 256>>>(N);
    deg_kernel<<<(E + 255) / 256, 256>>>(src, dst, E);

    // degree-sorted permutation + inverse + sorted-space norms
    hist_kernel<<<(N + 255) / 256, 256>>>(N);
    hist_scan_kernel<<<1, NBINS>>>();
    perm_kernel<<<(N + 255) / 256, 256>>>(N);
    inv_kernel<<<(N + 255) / 256, 256>>>(N);
    sdeg_kernel<<<(N + 255) / 256, 256>>>(N);

    // CSR build (sorted space)
    const int scanBlocks = (N + 255) / 256;
    scanA_kernel<<<scanBlocks, 256>>>(N);
    scanB_kernel<<<1, 512>>>(scanBlocks);
    scanC_kernel<<<scanBlocks, 256>>>(N);
    cursor_init_kernel<<<(N + 255) / 256, 256>>>(N);
    scatter_kernel<<<(E + 255) / 256, 256>>>(src, dst, E);

    // W1 pre-round + MLP
    w1_round_kernel<<<(IN_DIM * HID_DIM + 255) / 256, 256>>>(W1);
    dim3 g1(HID_DIM / 128, (N + 127) / 128);
    gemm1_mma_kernel<<<g1, 256>>>(feats, b1, N);
    gemm2_kernel<<<(N + 127) / 128, 256>>>(W2, b2, N);

    // propagation (sorted space)
    const int n4 = N * 12;
    h0perm_kernel<<<(n4 + 255) / 256, 256>>>(n4);
    hs0_kernel<<<(n4 + 255) / 256, 256>>>(n4);
    const int aggBlocks = (N * 12 + 383) / 384;
    for (int k = 0; k < 10; k++) {
        agg_kernel<<<aggBlocks, 384>>>((float*)d_out, k & 1, k == 9 ? 1 : 0, N);
    }
    (void)n_in; (void)out_size;
}

// round 17
// speedup vs baseline: 1.1504x; 1.1504x over previous
#include <cuda_runtime.h>
#include <cuda_fp16.h>
#include <cstdint>

// ---------------------------------------------------------------------------
// APPNP. GEMM1: tf32 mma.sync, CTA 128x128, 2-stage cp.async, B pre-rounded
// (RNA). Propagation: CSR(dst) + fused gather-reduce with fp16 hs buffers
// (halves gather traffic; accumulation in fp32; h0 and d_out stay fp32).
// ---------------------------------------------------------------------------

#define N_NODES 100000
#define E_EDGES 1600000
#define OUT_DIM 48
#define HID_DIM 256
#define IN_DIM  512

// Scratch (device globals — allocation APIs are forbidden)
__device__ __align__(16) float  g_hidden[(size_t)N_NODES * HID_DIM];
__device__ __align__(16) float  g_w1r[(size_t)IN_DIM * HID_DIM];   // RNA-rounded W1
__device__ __align__(16) float  g_h0[(size_t)N_NODES * OUT_DIM];
__device__ __align__(16) __half g_hsA[(size_t)N_NODES * OUT_DIM];  // fp16 ping
__device__ __align__(16) __half g_hsB[(size_t)N_NODES * OUT_DIM];  // fp16 pong
__device__ int   g_ideg_out[N_NODES];
__device__ int   g_ideg_in[N_NODES];
__device__ float g_norm_out[N_NODES];
__device__ float g_norm_in[N_NODES];
__device__ int   g_off[N_NODES + 1];
__device__ int   g_cursor[N_NODES];
__device__ int   g_blocksums[512];
__device__ int   g_csr_src[E_EDGES];

// ---------------------------------------------------------------------------
// Degrees / norms
// ---------------------------------------------------------------------------
__global__ void zero_deg_kernel(int n) {
    int i = blockIdx.x * blockDim.x + threadIdx.x;
    if (i < n) { g_ideg_out[i] = 0; g_ideg_in[i] = 0; }
}
__global__ void deg_kernel(const int* __restrict__ src, const int* __restrict__ dst, int e) {
    int i = blockIdx.x * blockDim.x + threadIdx.x;
    if (i < e) {
        atomicAdd(&g_ideg_out[src[i]], 1);
        atomicAdd(&g_ideg_in[dst[i]], 1);
    }
}
__global__ void norm_kernel(int n) {
    int i = blockIdx.x * blockDim.x + threadIdx.x;
    if (i < n) {
        g_norm_out[i] = rsqrtf((float)max(g_ideg_out[i], 1));
        g_norm_in[i]  = rsqrtf((float)max(g_ideg_in[i], 1));
    }
}

// ---------------------------------------------------------------------------
// Prefix sum over g_ideg_in -> g_off
// ---------------------------------------------------------------------------
__global__ void scanA_kernel(int n) {
    __shared__ int sh[256];
    int i = blockIdx.x * 256 + threadIdx.x;
    sh[threadIdx.x] = (i < n) ? g_ideg_in[i] : 0;
    __syncthreads();
#pragma unroll
    for (int d = 1; d < 256; d <<= 1) {
        int t = (threadIdx.x >= d) ? sh[threadIdx.x - d] : 0;
        __syncthreads();
        sh[threadIdx.x] += t;
        __syncthreads();
    }
    if (i < n) g_off[i + 1] = sh[threadIdx.x];
    if (threadIdx.x == 255) g_blocksums[blockIdx.x] = sh[255];
}
__global__ void scanB_kernel(int nb) {
    __shared__ int sh[512];
    int t = threadIdx.x;
    sh[t] = (t < nb) ? g_blocksums[t] : 0;
    __syncthreads();
#pragma unroll
    for (int d = 1; d < 512; d <<= 1) {
        int x = (t >= d) ? sh[t - d] : 0;
        __syncthreads();
        sh[t] += x;
        __syncthreads();
    }
    if (t < nb) g_blocksums[t] = sh[t];
}
__global__ void scanC_kernel(int n) {
    int i = blockIdx.x * 256 + threadIdx.x;
    if (i < n) {
        int add = (blockIdx.x > 0) ? g_blocksums[blockIdx.x - 1] : 0;
        g_off[i + 1] += add;
    }
    if (i == 0) g_off[0] = 0;
}
__global__ void cursor_init_kernel(int n) {
    int i = blockIdx.x * blockDim.x + threadIdx.x;
    if (i < n) g_cursor[i] = g_off[i];
}
__global__ void scatter_kernel(const int* __restrict__ src, const int* __restrict__ dst, int e) {
    int i = blockIdx.x * blockDim.x + threadIdx.x;
    if (i < e) {
        int p = atomicAdd(&g_cursor[dst[i]], 1);
        g_csr_src[p] = src[i];
    }
}

// ---------------------------------------------------------------------------
// tf32 helpers
// ---------------------------------------------------------------------------
__device__ __forceinline__ uint32_t rna_tf32_f(float x) {
    uint32_t u;
    asm("cvt.rna.tf32.f32 %0, %1;" : "=r"(u) : "f"(x));
    return u;
}
__device__ __forceinline__ void mma_tf32(float c[4],
                                         uint32_t a0, uint32_t a1, uint32_t a2, uint32_t a3,
                                         uint32_t b0, uint32_t b1)
{
    asm volatile(
        "mma.sync.aligned.m16n8k8.row.col.f32.tf32.tf32.f32 "
        "{%0,%1,%2,%3}, {%4,%5,%6,%7}, {%8,%9}, {%0,%1,%2,%3};"
        : "+f"(c[0]), "+f"(c[1]), "+f"(c[2]), "+f"(c[3])
        : "r"(a0), "r"(a1), "r"(a2), "r"(a3), "r"(b0), "r"(b1));
}
__device__ __forceinline__ uint32_t smem_u32(const void* p) {
    uint32_t a;
    asm("{ .reg .u64 t; cvta.to.shared.u64 t, %1; cvt.u32.u64 %0, t; }" : "=r"(a) : "l"(p));
    return a;
}
__device__ __forceinline__ void cp16(uint32_t dst, const void* src, int szbytes) {
    asm volatile("cp.async.cg.shared.global [%0], [%1], 16, %2;"
                 :: "r"(dst), "l"(src), "r"(szbytes));
}
#define CP_COMMIT() asm volatile("cp.async.commit_group;" ::: "memory")
#define CP_WAIT(n)  asm volatile("cp.async.wait_group %0;" :: "n"(n) : "memory")

// W1 pre-round (RNA): mma's RZ truncation of this is the identity
__global__ void w1_round_kernel(const float* __restrict__ W1) {
    int i = blockIdx.x * blockDim.x + threadIdx.x;
    if (i < IN_DIM * HID_DIM)
        g_w1r[i] = __uint_as_float(rna_tf32_f(W1[i]));
}

// ---------------------------------------------------------------------------
// GEMM1 (tf32 mma.sync, 2-stage cp.async, CTA 128x128 — exact R15 structure)
// ---------------------------------------------------------------------------
#define G1_AS_STRIDE 20
#define G1_BS_STRIDE 136
#define G1_NCHUNK    (IN_DIM / 16)   // 32

__global__ __launch_bounds__(256, 2) void gemm1_mma_kernel(
    const float* __restrict__ A, const float* __restrict__ bias, int M)
{
    __shared__ uint32_t As[2][128][G1_AS_STRIDE];
    __shared__ uint32_t Bs[2][16][G1_BS_STRIDE];

    const int tid  = threadIdx.x;
    const int wid  = tid >> 5;
    const int lane = tid & 31;
    const int warpM = wid & 3;
    const int warpN = wid >> 2;
    const int m0 = blockIdx.y * 128;
    const int n0 = blockIdx.x * 128;

    const int grp = lane >> 2;
    const int qid = lane & 3;

    const int a_m0 = tid >> 2;
    const int a_k0 = (tid & 3) * 4;
    const int a_m1 = (tid + 256) >> 2;
    const int a_k1 = ((tid + 256) & 3) * 4;
    const int b_kk0 = tid >> 5;
    const int b_nn0 = (tid & 31) * 4;
    const int b_kk1 = (tid + 256) >> 5;
    const int b_nn1 = ((tid + 256) & 31) * 4;

    float acc[2][8][4];
#pragma unroll
    for (int mt = 0; mt < 2; mt++)
#pragma unroll
        for (int nt = 0; nt < 8; nt++)
#pragma unroll
            for (int q = 0; q < 4; q++) acc[mt][nt][q] = 0.f;

    auto issue = [&](int kc, int b) {
        const int k0 = kc * 16;
        const uint32_t abase = smem_u32(&As[b][0][0]);
        const uint32_t bbase = smem_u32(&Bs[b][0][0]);
        int sz0 = (m0 + a_m0 < M) ? 16 : 0;
        cp16(abase + (uint32_t)(a_m0 * G1_AS_STRIDE + a_k0) * 4,
             &A[(size_t)(m0 + a_m0) * IN_DIM + k0 + a_k0], sz0);
        int sz1 = (m0 + a_m1 < M) ? 16 : 0;
        cp16(abase + (uint32_t)(a_m1 * G1_AS_STRIDE + a_k1) * 4,
             &A[(size_t)(m0 + a_m1) * IN_DIM + k0 + a_k1], sz1);
        cp16(bbase + (uint32_t)(b_kk0 * G1_BS_STRIDE + b_nn0) * 4,
             &g_w1r[(size_t)(k0 + b_kk0) * HID_DIM + n0 + b_nn0], 16);
        cp16(bbase + (uint32_t)(b_kk1 * G1_BS_STRIDE + b_nn1) * 4,
             &g_w1r[(size_t)(k0 + b_kk1) * HID_DIM + n0 + b_nn1], 16);
        CP_COMMIT();
    };

    issue(0, 0);
    issue(1, 1);

    for (int kc = 0; kc < G1_NCHUNK; kc++) {
        const int b = kc & 1;
        if (kc + 1 < G1_NCHUNK) { CP_WAIT(1); } else { CP_WAIT(0); }
        __syncthreads();

#pragma unroll
        for (int ks = 0; ks < 2; ks++) {
            const int k = ks * 8;
            uint32_t bf[8][2];
#pragma unroll
            for (int nt = 0; nt < 8; nt++) {
                int cn = warpN * 64 + nt * 8 + grp;
                bf[nt][0] = Bs[b][k + qid][cn];
                bf[nt][1] = Bs[b][k + 4 + qid][cn];
            }
#pragma unroll
            for (int mt = 0; mt < 2; mt++) {
                int rm = warpM * 32 + mt * 16 + grp;
                uint32_t a0 = As[b][rm][k + qid];
                uint32_t a1 = As[b][rm + 8][k + qid];
                uint32_t a2 = As[b][rm][k + 4 + qid];
                uint32_t a3 = As[b][rm + 8][k + 4 + qid];
#pragma unroll
                for (int nt = 0; nt < 8; nt++)
                    mma_tf32(acc[mt][nt], a0, a1, a2, a3, bf[nt][0], bf[nt][1]);
            }
        }
        __syncthreads();
        if (kc + 2 < G1_NCHUNK) issue(kc + 2, b);
    }

#pragma unroll
    for (int nt = 0; nt < 8; nt++) {
        int col = n0 + warpN * 64 + nt * 8 + 2 * qid;
        float bb0 = __ldg(&bias[col]);
        float bb1 = __ldg(&bias[col + 1]);
#pragma unroll
        for (int mt = 0; mt < 2; mt++) {
            int r0 = m0 + warpM * 32 + mt * 16 + grp;
            if (r0 < M) {
                float2 v = make_float2(fmaxf(acc[mt][nt][0] + bb0, 0.f),
                                       fmaxf(acc[mt][nt][1] + bb1, 0.f));
                *(float2*)&g_hidden[(size_t)r0 * HID_DIM + col] = v;
            }
            if (r0 + 8 < M) {
                float2 v = make_float2(fmaxf(acc[mt][nt][2] + bb0, 0.f),
                                       fmaxf(acc[mt][nt][3] + bb1, 0.f));
                *(float2*)&g_hidden[(size_t)(r0 + 8) * HID_DIM + col] = v;
            }
        }
    }
}

// ---------------------------------------------------------------------------
// GEMM2: h0 = hidden[M,256] @ W2[256,48] + b2  (SIMT)
// ---------------------------------------------------------------------------
__global__ __launch_bounds__(256) void gemm2_kernel(
    const float* __restrict__ W2, const float* __restrict__ b2, int M)
{
    __shared__ float Ws[64][48];
    const int tid = threadIdx.x;
    const int row = blockIdx.x * 128 + (tid >> 1);
    const int half = tid & 1;
    const bool ok = (row < M);

    float acc[24];
#pragma unroll
    for (int j = 0; j < 24; j++) acc[j] = 0.f;

    const float4* hid4 = (const float4*)g_hidden;
    for (int kc = 0; kc < 4; kc++) {
        __syncthreads();
        for (int i = tid; i < 64 * 48; i += 256) {
            int kk = i / 48, c = i - kk * 48;
            Ws[kk][c] = W2[(kc * 64 + kk) * 48 + c];
        }
        __syncthreads();
        if (ok) {
#pragma unroll
            for (int k4 = 0; k4 < 16; k4++) {
                float4 a = hid4[(size_t)row * 64 + kc * 16 + k4];
                float av[4] = {a.x, a.y, a.z, a.w};
#pragma unroll
                for (int q = 0; q < 4; q++)
#pragma unroll
                    for (int j = 0; j < 24; j++)
                        acc[j] += av[q] * Ws[k4 * 4 + q][half * 24 + j];
            }
        }
    }
    if (ok) {
#pragma unroll
        for (int j = 0; j < 24; j++)
            g_h0[(size_t)row * 48 + half * 24 + j] = acc[j] + b2[half * 24 + j];
    }
}

// ---------------------------------------------------------------------------
// Propagation (CSR, fused, atomic-free, fp16 hs)
// Each node row = 48 halves = 96 B = 6 uint4 chunks; 6 threads per node.
// ---------------------------------------------------------------------------
// hs0 = half(h0 * norm_out)
__global__ void hs0_kernel(int n6) {
    int i = blockIdx.x * blockDim.x + threadIdx.x;
    if (i >= n6) return;
    int row = i / 6, c = i - row * 6;
    float no = g_norm_out[row];
    float4 v0 = ((const float4*)g_h0)[(size_t)row * 12 + c * 2];
    float4 v1 = ((const float4*)g_h0)[(size_t)row * 12 + c * 2 + 1];
    __half2 h[4];
    h[0] = __floats2half2_rn(v0.x * no, v0.y * no);
    h[1] = __floats2half2_rn(v0.z * no, v0.w * no);
    h[2] = __floats2half2_rn(v1.x * no, v1.y * no);
    h[3] = __floats2half2_rn(v1.z * no, v1.w * no);
    ((uint4*)g_hsA)[i] = *(uint4*)h;
}

__global__ __launch_bounds__(384) void agg_kernel(
    float* __restrict__ dout, int parity, int last, int n)
{
    int t = blockIdx.x * 384 + threadIdx.x;
    int g = t / 6;
    int c = t - g * 6;
    if (g >= n) return;

    const uint4* hin  = (const uint4*)(parity ? g_hsB : g_hsA);
    uint4*       hout = (uint4*)(parity ? g_hsA : g_hsB);

    int i   = g_off[g];
    int end = g_off[g + 1];
    float acc[8];
#pragma unroll
    for (int j = 0; j < 8; j++) acc[j] = 0.f;

    for (; i + 3 < end; i += 4) {
        int s0 = __ldg(&g_csr_src[i]);
        int s1 = __ldg(&g_csr_src[i + 1]);
        int s2 = __ldg(&g_csr_src[i + 2]);
        int s3 = __ldg(&g_csr_src[i + 3]);
        uint4 v0 = hin[(size_t)s0 * 6 + c];
        uint4 v1 = hin[(size_t)s1 * 6 + c];
        uint4 v2 = hin[(size_t)s2 * 6 + c];
        uint4 v3 = hin[(size_t)s3 * 6 + c];
        const __half2* p0 = (const __half2*)&v0;
        const __half2* p1 = (const __half2*)&v1;
        const __half2* p2 = (const __half2*)&v2;
        const __half2* p3 = (const __half2*)&v3;
#pragma unroll
        for (int j = 0; j < 4; j++) {
            float2 f0 = __half22float2(p0[j]);
            float2 f1 = __half22float2(p1[j]);
            float2 f2 = __half22float2(p2[j]);
            float2 f3 = __half22float2(p3[j]);
            acc[2 * j]     += (f0.x + f1.x) + (f2.x + f3.x);
            acc[2 * j + 1] += (f0.y + f1.y) + (f2.y + f3.y);
        }
    }
    for (; i < end; i++) {
        int s = __ldg(&g_csr_src[i]);
        uint4 v = hin[(size_t)s * 6 + c];
        const __half2* p = (const __half2*)&v;
#pragma unroll
        for (int j = 0; j < 4; j++) {
            float2 f = __half22float2(p[j]);
            acc[2 * j]     += f.x;
            acc[2 * j + 1] += f.y;
        }
    }

    float ni = g_norm_in[g];
    float4 z0 = ((const float4*)g_h0)[(size_t)g * 12 + c * 2];
    float4 z1 = ((const float4*)g_h0)[(size_t)g * 12 + c * 2 + 1];
    float h[8];
    h[0] = 0.9f * acc[0] * ni + 0.1f * z0.x;
    h[1] = 0.9f * acc[1] * ni + 0.1f * z0.y;
    h[2] = 0.9f * acc[2] * ni + 0.1f * z0.z;
    h[3] = 0.9f * acc[3] * ni + 0.1f * z0.w;
    h[4] = 0.9f * acc[4] * ni + 0.1f * z1.x;
    h[5] = 0.9f * acc[5] * ni + 0.1f * z1.y;
    h[6] = 0.9f * acc[6] * ni + 0.1f * z1.z;
    h[7] = 0.9f * acc[7] * ni + 0.1f * z1.w;

    if (last) {
        ((float4*)dout)[(size_t)g * 12 + c * 2]     = make_float4(h[0], h[1], h[2], h[3]);
        ((float4*)dout)[(size_t)g * 12 + c * 2 + 1] = make_float4(h[4], h[5], h[6], h[7]);
    } else {
        float no = g_norm_out[g];
        __half2 o[4];
        o[0] = __floats2half2_rn(h[0] * no, h[1] * no);
        o[1] = __floats2half2_rn(h[2] * no, h[3] * no);
        o[2] = __floats2half2_rn(h[4] * no, h[5] * no);
        o[3] = __floats2half2_rn(h[6] * no, h[7] * no);
        hout[(size_t)g * 6 + c] = *(uint4*)o;
    }
}

// ---------------------------------------------------------------------------
extern "C" void kernel_launch(void* const* d_in, const int* in_sizes, int n_in,
                              void* d_out, int out_size)
{
    const float* feats = (const float*)d_in[0];
    const int*   src   = (const int*)d_in[1];
    const int*   dst   = (const int*)d_in[2];
    const float* W1    = (const float*)d_in[3];
    const float* b1    = (const float*)d_in[4];
    const float* W2    = (const float*)d_in[5];
    const float* b2    = (const float*)d_in[6];

    const int N = in_sizes[0] / IN_DIM;
    const int E = in_sizes[1];

    // degrees + norms
    zero_deg_kernel<<<(N + 255) / 256, 256>>>(N);
    deg_kernel<<<(E + 255) / 256, 256>>>(src, dst, E);
    norm_kernel<<<(N + 255) / 256, 256>>>(N);

    // CSR build (by dst)
    const int scanBlocks = (N + 255) / 256;
    scanA_kernel<<<scanBlocks, 256>>>(N);
    scanB_kernel<<<1, 512>>>(scanBlocks);
    scanC_kernel<<<scanBlocks, 256>>>(N);
    cursor_init_kernel<<<(N + 255) / 256, 256>>>(N);
    scatter_kernel<<<(E + 255) / 256, 256>>>(src, dst, E);

    // W1 pre-round + MLP
    w1_round_kernel<<<(IN_DIM * HID_DIM + 255) / 256, 256>>>(W1);
    dim3 g1(HID_DIM / 128, (N + 127) / 128);
    gemm1_mma_kernel<<<g1, 256>>>(feats, b1, N);
    gemm2_kernel<<<(N + 127) / 128, 256>>>(W2, b2, N);

    // propagation (fp16 hs)
    const int n6 = N * 6;
    hs0_kernel<<<(n6 + 255) / 256, 256>>>(n6);
    const int aggBlocks = (n6 + 383) / 384;
    for (int k = 0; k < 10; k++) {
        agg_kernel<<<aggBlocks, 384>>>((float*)d_out, k & 1, k == 9 ? 1 : 0, N);
    }
    (void)n_in; (void)out_size;
}